// round 8
// baseline (speedup 1.0000x reference)
#include <cuda_runtime.h>
#include <math.h>
#include <stdint.h>

#define CHI 64
#define CHO 64
#define B_  4
#define H_  128
#define W_  256
#define HW  (H_*W_)

#define SAS 68          // smem row stride (floats)

// dcn_main smem: A 128x68, Bh 64x68, Bl 64x68
#define DM_A   0
#define DM_BH  8704
#define DM_BL  (8704 + 4352)
#define DM_TOTAL ((8704 + 4352 + 4352) * 4)     // 69632 B

// offset conv smem: A 128x68, Bh 32x68, Bl 32x68
#define OC_A   0
#define OC_BH  8704
#define OC_BL  (8704 + 2176)
#define OC_TOTAL ((8704 + 2176 + 2176) * 4)     // 52224 B

// scratch: offset/mask conv output [B, 27, H, W]
__device__ float g_om[(size_t)B_ * 27 * H_ * W_];
// main weight pre-split tf32: [tap][co][ci]
__device__ float g_wBh[9 * CHO * CHI];
__device__ float g_wBl[9 * CHO * CHI];
// offset weight pre-split tf32: [tap][32(oc pad)][ci]
__device__ float g_wOh[9 * 32 * CHI];
__device__ float g_wOl[9 * 32 * CHI];

// ---------------------------------------------------------------------------
__device__ __forceinline__ uint32_t f2tf32(float x) {
    uint32_t u; asm("cvt.rna.tf32.f32 %0, %1;" : "=r"(u) : "f"(x)); return u;
}
__device__ __forceinline__ void split_tf32(float v, uint32_t& hi, uint32_t& lo) {
    uint32_t h = f2tf32(v);
    float r = v - __uint_as_float(h);
    hi = h;
    lo = f2tf32(r);
}
__device__ __forceinline__ void mma8(float* d, const uint32_t* a,
                                     uint32_t b0, uint32_t b1) {
    asm volatile(
        "mma.sync.aligned.m16n8k8.row.col.f32.tf32.tf32.f32 "
        "{%0,%1,%2,%3}, {%4,%5,%6,%7}, {%8,%9}, {%0,%1,%2,%3};"
        : "+f"(d[0]), "+f"(d[1]), "+f"(d[2]), "+f"(d[3])
        : "r"(a[0]), "r"(a[1]), "r"(a[2]), "r"(a[3]), "r"(b0), "r"(b1));
}

// ---------------------------------------------------------------------------
// prep: split both weight tensors to tf32 hi/lo in GEMM-ready layouts
// ---------------------------------------------------------------------------
__global__ void prep_weights_kernel(const float* __restrict__ w,
                                    const float* __restrict__ w_off)
{
    int i = blockIdx.x * 256 + threadIdx.x;
    if (i < 9 * 64 * 64) {                        // main weight
        int tap = i / 4096;
        int rem = i - tap * 4096;
        int co  = rem >> 6;
        int ci  = rem & 63;
        float val = w[(co * 64 + ci) * 9 + tap];
        uint32_t hi, lo;
        split_tf32(val, hi, lo);
        g_wBh[tap * 4096 + co * 64 + ci] = __uint_as_float(hi);
        g_wBl[tap * 4096 + co * 64 + ci] = __uint_as_float(lo);
    } else if (i < 9 * 64 * 64 + 9 * 32 * 64) {   // offset weight (oc padded to 32)
        int j   = i - 9 * 64 * 64;
        int tap = j / 2048;
        int rem = j - tap * 2048;
        int oc  = rem >> 6;
        int ci  = rem & 63;
        float val = (oc < 27) ? w_off[(oc * 64 + ci) * 9 + tap] : 0.0f;
        uint32_t hi, lo;
        split_tf32(val, hi, lo);
        g_wOh[tap * 2048 + oc * 64 + ci] = __uint_as_float(hi);
        g_wOl[tap * 2048 + oc * 64 + ci] = __uint_as_float(lo);
    }
}

// ---------------------------------------------------------------------------
// Kernel 1: offset/mask conv as tf32 MMA implicit GEMM.
// 256 threads: warp w -> m-block (w&3, 32 pix) x n-half (w>>2, 16 oc).
// Gather: threads 0-127 load ci 0-31, threads 128-255 load ci 32-63.
// ---------------------------------------------------------------------------
__global__ __launch_bounds__(256, 3) void offset_conv_kernel(
    const float* __restrict__ x,
    const float* __restrict__ b_off)
{
    extern __shared__ float smf[];
    float* As  = smf + OC_A;
    float* Bhs = smf + OC_BH;
    float* Bls = smf + OC_BL;

    const int tid  = threadIdx.x;
    const int wid  = tid >> 5;
    const int lid  = tid & 31;
    const int g    = lid >> 2;
    const int t    = lid & 3;
    const int mb   = wid & 3;      // m-block (32 pixels)
    const int nh   = wid >> 2;     // n-half (16 oc)
    const int pix  = tid & 127;    // gather pixel
    const int ch   = tid >> 7;     // ci half (0: ci 0-31, 1: ci 32-63)
    const int hblk = blockIdx.x;
    const int h    = blockIdx.y;
    const int b    = blockIdx.z;
    const int wo   = hblk * 128 + pix;

    const float* xb = x + (size_t)b * CHI * HW;

    float acc[2][2][4];
    #pragma unroll
    for (int m = 0; m < 2; m++)
        #pragma unroll
        for (int n = 0; n < 2; n++)
            #pragma unroll
            for (int e = 0; e < 4; e++) acc[m][n][e] = 0.0f;

    #pragma unroll 1
    for (int tap = 0; tap < 9; tap++) {
        if (tap) __syncthreads();

        // ---- copy pre-split B tiles [32oc][64ci] -> smem stride 68 ----
        {
            const float4* bh = (const float4*)(g_wOh + tap * 2048);
            const float4* bl = (const float4*)(g_wOl + tap * 2048);
            #pragma unroll
            for (int j = 0; j < 2; j++) {
                const int lin = tid + j * 256;      // 512 float4 total
                const int oc  = lin >> 4;
                const int c4  = lin & 15;
                *(float4*)(Bhs + oc * SAS + c4 * 4) = bh[lin];
                *(float4*)(Bls + oc * SAS + c4 * 4) = bl[lin];
            }
        }

        // ---- A tile: shifted input, zero-padded borders (32 ci/thread) ----
        const int y  = h  - 1 + tap / 3;
        const int xv = wo - 1 + tap % 3;
        const bool valid = (y >= 0) && (y < H_) && (xv >= 0) && (xv < W_);
        const float* xp = xb + y * W_ + xv + ch * 32 * HW;
        #pragma unroll
        for (int j = 0; j < 8; j++) {
            float4 v4;
            #pragma unroll
            for (int e = 0; e < 4; e++)
                ((float*)&v4)[e] = valid ? __ldg(xp + (j * 4 + e) * HW) : 0.0f;
            *(float4*)(As + pix * SAS + ch * 32 + j * 4) = v4;
        }

        __syncthreads();

        // ---- MMA: 8 k-steps x 2 n-frags x (2m x 3 terms) ----
        #pragma unroll 1
        for (int kk = 0; kk < 8; kk++) {
            const int col = kk * 8 + t;
            uint32_t ah[2][4], al[2][4];
            #pragma unroll
            for (int mi = 0; mi < 2; mi++) {
                const float* ab = As + (mb * 32 + mi * 16 + g) * SAS + col;
                split_tf32(ab[0],           ah[mi][0], al[mi][0]);
                split_tf32(ab[8 * SAS],     ah[mi][1], al[mi][1]);
                split_tf32(ab[4],           ah[mi][2], al[mi][2]);
                split_tf32(ab[8 * SAS + 4], ah[mi][3], al[mi][3]);
            }
            #pragma unroll
            for (int n = 0; n < 2; n++) {
                const float* bh = Bhs + (nh * 16 + n * 8 + g) * SAS + col;
                const float* bl = Bls + (nh * 16 + n * 8 + g) * SAS + col;
                const uint32_t bh0 = __float_as_uint(bh[0]);
                const uint32_t bh1 = __float_as_uint(bh[4]);
                const uint32_t bl0 = __float_as_uint(bl[0]);
                const uint32_t bl1 = __float_as_uint(bl[4]);
                mma8(acc[0][n], ah[0], bh0, bh1);
                mma8(acc[1][n], ah[1], bh0, bh1);
                mma8(acc[0][n], al[0], bh0, bh1);
                mma8(acc[1][n], al[1], bh0, bh1);
                mma8(acc[0][n], ah[0], bl0, bl1);
                mma8(acc[1][n], ah[1], bl0, bl1);
            }
        }
    }

    // ---- epilogue: stage through warp's own region of As ----
    __syncthreads();
    float* ds = As + wid * 544;       // [16 oc][34]
    #pragma unroll
    for (int mi = 0; mi < 2; mi++) {
        #pragma unroll
        for (int n = 0; n < 2; n++) {
            const int oc = n * 8 + 2 * t;
            const int p  = mi * 16 + g;
            ds[oc * 34 + p]           = acc[mi][n][0];
            ds[(oc + 1) * 34 + p]     = acc[mi][n][1];
            ds[oc * 34 + p + 8]       = acc[mi][n][2];
            ds[(oc + 1) * 34 + p + 8] = acc[mi][n][3];
        }
    }
    __syncwarp();

    const int pixbase = hblk * 128 + mb * 32;
    #pragma unroll
    for (int cl = 0; cl < 16; cl++) {
        const int oc = nh * 16 + cl;
        if (oc < 27) {
            g_om[((size_t)(b * 27 + oc) * H_ + h) * W_ + pixbase + lid] =
                ds[cl * 34 + lid] + __ldg(b_off + oc);
        }
    }
}

// ---------------------------------------------------------------------------
// Kernel 2: deformable conv main GEMM on mma.sync tf32 (3-term split).
// 256 threads: warp w -> m-block (w&3, 32 pix) x n-half (w>>2, 32 co).
// Gather: threads 0-127 bilinear ci 0-31, threads 128-255 ci 32-63.
// ---------------------------------------------------------------------------
__global__ __launch_bounds__(256, 2) void dcn_main_kernel(
    const float* __restrict__ x,
    const float* __restrict__ bias,
    float* __restrict__ out)
{
    extern __shared__ float smf[];
    float* As  = smf + DM_A;
    float* Bhs = smf + DM_BH;
    float* Bls = smf + DM_BL;

    const int tid  = threadIdx.x;
    const int wid  = tid >> 5;
    const int lid  = tid & 31;
    const int g    = lid >> 2;
    const int t    = lid & 3;
    const int mb   = wid & 3;      // m-block (32 pixels)
    const int nh   = wid >> 2;     // n-half (32 co)
    const int pix  = tid & 127;    // gather pixel
    const int ch   = tid >> 7;     // ci half
    const int hblk = blockIdx.x;
    const int h    = blockIdx.y;
    const int b    = blockIdx.z;
    const int wo   = hblk * 128 + pix;

    const float* omp = g_om + ((size_t)b * 27 * H_ + h) * W_ + wo;
    const float* xb  = x + (size_t)b * CHI * HW + (size_t)ch * 32 * HW;

    float acc[2][4][4];
    #pragma unroll
    for (int m = 0; m < 2; m++)
        #pragma unroll
        for (int n = 0; n < 4; n++)
            #pragma unroll
            for (int e = 0; e < 4; e++) acc[m][n][e] = 0.0f;

    #pragma unroll 1
    for (int tap = 0; tap < 9; tap++) {
        if (tap) __syncthreads();

        // ---- copy pre-split B tiles [64co][64ci] -> smem stride 68 ----
        {
            const float4* bh = (const float4*)(g_wBh + tap * 4096);
            const float4* bl = (const float4*)(g_wBl + tap * 4096);
            #pragma unroll
            for (int j = 0; j < 4; j++) {
                const int lin = tid + j * 256;      // 1024 float4 total
                const int co  = lin >> 4;
                const int c4  = lin & 15;
                *(float4*)(Bhs + co * SAS + c4 * 4) = bh[lin];
                *(float4*)(Bls + co * SAS + c4 * 4) = bl[lin];
            }
        }

        // ---- sampling params for this thread's pixel ----
        const float oy = omp[(size_t)(2 * tap)     * HW];
        const float ox = omp[(size_t)(2 * tap + 1) * HW];
        const float mz = omp[(size_t)(18 + tap)    * HW];
        const float m  = 1.0f / (1.0f + expf(-mz));

        const float sy = (float)(h  - 1 + tap / 3) + oy;
        const float sx = (float)(wo - 1 + tap % 3) + ox;

        const float y0f = floorf(sy);
        const float x0f = floorf(sx);
        const float dy  = sy - y0f;
        const float dx  = sx - x0f;
        const int y0 = (int)y0f, x0 = (int)x0f;
        const int y1 = y0 + 1,  x1 = x0 + 1;

        const bool vy0 = (y0 >= 0) && (y0 < H_);
        const bool vy1 = (y1 >= 0) && (y1 < H_);
        const bool vx0 = (x0 >= 0) && (x0 < W_);
        const bool vx1 = (x1 >= 0) && (x1 < W_);

        float w00 = (1.0f - dy) * (1.0f - dx) * m;
        float w01 = (1.0f - dy) * dx * m;
        float w10 = dy * (1.0f - dx) * m;
        float w11 = dy * dx * m;
        if (!(vy0 && vx0)) w00 = 0.0f;
        if (!(vy0 && vx1)) w01 = 0.0f;
        if (!(vy1 && vx0)) w10 = 0.0f;
        if (!(vy1 && vx1)) w11 = 0.0f;

        const int cy0 = min(max(y0, 0), H_ - 1);
        const int cy1 = min(max(y1, 0), H_ - 1);
        const int cx0 = min(max(x0, 0), W_ - 1);
        const int cx1 = min(max(x1, 0), W_ - 1);

        const float* p00 = xb + cy0 * W_ + cx0;
        const float* p01 = xb + cy0 * W_ + cx1;
        const float* p10 = xb + cy1 * W_ + cx0;
        const float* p11 = xb + cy1 * W_ + cx1;

        // ---- gather + bilinear: 32 ci for this pixel -> A[pix][ch*32..] ----
        #pragma unroll
        for (int j = 0; j < 8; j++) {
            float4 v4;
            #pragma unroll
            for (int e = 0; e < 4; e++) {
                const int ci = j * 4 + e;
                ((float*)&v4)[e] = w00 * __ldg(p00 + ci * HW)
                                 + w01 * __ldg(p01 + ci * HW)
                                 + w10 * __ldg(p10 + ci * HW)
                                 + w11 * __ldg(p11 + ci * HW);
            }
            *(float4*)(As + pix * SAS + ch * 32 + j * 4) = v4;
        }

        __syncthreads();

        // ---- MMA: 8 k-steps x 4 n-frags x (2m x 3 terms) ----
        #pragma unroll 1
        for (int kk = 0; kk < 8; kk++) {
            const int col = kk * 8 + t;
            uint32_t ah[2][4], al[2][4];
            #pragma unroll
            for (int mi = 0; mi < 2; mi++) {
                const float* ab = As + (mb * 32 + mi * 16 + g) * SAS + col;
                split_tf32(ab[0],           ah[mi][0], al[mi][0]);
                split_tf32(ab[8 * SAS],     ah[mi][1], al[mi][1]);
                split_tf32(ab[4],           ah[mi][2], al[mi][2]);
                split_tf32(ab[8 * SAS + 4], ah[mi][3], al[mi][3]);
            }
            #pragma unroll
            for (int n = 0; n < 4; n++) {
                const float* bh = Bhs + (nh * 32 + n * 8 + g) * SAS + col;
                const float* bl = Bls + (nh * 32 + n * 8 + g) * SAS + col;
                const uint32_t bh0 = __float_as_uint(bh[0]);
                const uint32_t bh1 = __float_as_uint(bh[4]);
                const uint32_t bl0 = __float_as_uint(bl[0]);
                const uint32_t bl1 = __float_as_uint(bl[4]);
                mma8(acc[0][n], ah[0], bh0, bh1);
                mma8(acc[1][n], ah[1], bh0, bh1);
                mma8(acc[0][n], al[0], bh0, bh1);
                mma8(acc[1][n], al[1], bh0, bh1);
                mma8(acc[0][n], ah[0], bl0, bl1);
                mma8(acc[1][n], ah[1], bl0, bl1);
            }
        }
    }

    // ---- epilogue: stage D through warp's own region of As ----
    __syncthreads();
    float* ds = As + wid * 1088;           // [32 co][34] per warp
    #pragma unroll
    for (int mi = 0; mi < 2; mi++) {
        #pragma unroll
        for (int n = 0; n < 4; n++) {
            const int co = n * 8 + 2 * t;
            const int p  = mi * 16 + g;
            ds[co * 34 + p]           = acc[mi][n][0];
            ds[(co + 1) * 34 + p]     = acc[mi][n][1];
            ds[co * 34 + p + 8]       = acc[mi][n][2];
            ds[(co + 1) * 34 + p + 8] = acc[mi][n][3];
        }
    }
    __syncwarp();

    const int pixbase = hblk * 128 + mb * 32;
    #pragma unroll 8
    for (int cl = 0; cl < 32; cl++) {
        const int co = nh * 32 + cl;
        out[((size_t)(b * CHO + co) * H_ + h) * W_ + pixbase + lid] =
            ds[cl * 34 + lid] + __ldg(bias + co);
    }
}

// ---------------------------------------------------------------------------
extern "C" void kernel_launch(void* const* d_in, const int* in_sizes, int n_in,
                              void* d_out, int out_size)
{
    const float* x      = (const float*)d_in[0];
    const float* w_off  = (const float*)d_in[1];
    const float* b_off  = (const float*)d_in[2];
    const float* weight = (const float*)d_in[3];
    const float* bias   = (const float*)d_in[4];
    float* out = (float*)d_out;

    cudaFuncSetAttribute(offset_conv_kernel,
                         cudaFuncAttributeMaxDynamicSharedMemorySize, OC_TOTAL);
    cudaFuncSetAttribute(dcn_main_kernel,
                         cudaFuncAttributeMaxDynamicSharedMemorySize, DM_TOTAL);

    const int prep_n = 9 * 64 * 64 + 9 * 32 * 64;
    prep_weights_kernel<<<(prep_n + 255) / 256, 256>>>(weight, w_off);
    offset_conv_kernel<<<dim3(2, H_, B_), 256, OC_TOTAL>>>(x, b_off);
    dcn_main_kernel<<<dim3(2, H_, B_), 256, DM_TOTAL>>>(x, bias, out);
}

// round 9
// speedup vs baseline: 1.1297x; 1.1297x over previous
#include <cuda_runtime.h>
#include <math.h>
#include <stdint.h>

#define CHI 64
#define CHO 64
#define B_  4
#define H_  128
#define W_  256
#define HW  (H_*W_)

#define SAS 68          // smem A row stride (floats)

// packed-B strides (floats)
#define DM_ST  264                  // t-block stride, main (>=256, ==8 mod 32)
#define DM_SK  (4*DM_ST)            // 1056 per kk
#define DM_TAP (8*DM_SK)            // 8448 per tap
#define OC_ST  136                  // t-block stride, offset (>=128, ==8 mod 32)
#define OC_SK  (4*OC_ST)            // 544
#define OC_TAP (8*OC_SK)            // 4352

// dcn_main smem: A 128x68 (8704 fl) + Bp 8448 fl = 17152 fl = 68608 B
#define DM_A   0
#define DM_BP  8704
#define DM_TOTAL ((8704 + DM_TAP) * 4)
// offset smem: A 8704 fl + Bp 4352 fl = 13056 fl = 52224 B
#define OC_A   0
#define OC_BP  8704
#define OC_TOTAL ((8704 + OC_TAP) * 4)

// scratch: offset/mask conv output [B, 27, H, W]
__device__ float g_om[(size_t)B_ * 27 * H_ * W_];
// quad-packed pre-split weights
__device__ float g_wBp[9 * DM_TAP];
__device__ float g_wOp[9 * OC_TAP];

// ---------------------------------------------------------------------------
__device__ __forceinline__ uint32_t f2tf32(float x) {
    uint32_t u; asm("cvt.rna.tf32.f32 %0, %1;" : "=r"(u) : "f"(x)); return u;
}
__device__ __forceinline__ void split_tf32(float v, uint32_t& hi, uint32_t& lo) {
    uint32_t h = f2tf32(v);
    float r = v - __uint_as_float(h);
    hi = h;
    lo = f2tf32(r);
}
__device__ __forceinline__ void mma8(float* d, const uint32_t* a,
                                     uint32_t b0, uint32_t b1) {
    asm volatile(
        "mma.sync.aligned.m16n8k8.row.col.f32.tf32.tf32.f32 "
        "{%0,%1,%2,%3}, {%4,%5,%6,%7}, {%8,%9}, {%0,%1,%2,%3};"
        : "+f"(d[0]), "+f"(d[1]), "+f"(d[2]), "+f"(d[3])
        : "r"(a[0]), "r"(a[1]), "r"(a[2]), "r"(a[3]), "r"(b0), "r"(b1));
}

// ---------------------------------------------------------------------------
// prep: build quad-packed tf32 hi/lo weight images.
// quad(tap,kk,t,co) = {Bh[co][8kk+t], Bh[co][8kk+t+4], Bl[co][8kk+t], Bl[co][8kk+t+4]}
// ---------------------------------------------------------------------------
__global__ void prep_weights_kernel(const float* __restrict__ w,
                                    const float* __restrict__ w_off)
{
    int i = blockIdx.x * 256 + threadIdx.x;
    if (i < 9 * 64 * 32) {                        // main: (tap, co, kk, t)
        int tap = i / 2048;
        int rem = i - tap * 2048;
        int co  = rem >> 5;
        int kk  = (rem >> 2) & 7;
        int t   = rem & 3;
        int ci0 = kk * 8 + t;
        float v0 = w[(co * 64 + ci0)     * 9 + tap];
        float v1 = w[(co * 64 + ci0 + 4) * 9 + tap];
        uint32_t h0, l0, h1, l1;
        split_tf32(v0, h0, l0);
        split_tf32(v1, h1, l1);
        float* q = g_wBp + (size_t)tap * DM_TAP + kk * DM_SK + t * DM_ST + co * 4;
        q[0] = __uint_as_float(h0);
        q[1] = __uint_as_float(h1);
        q[2] = __uint_as_float(l0);
        q[3] = __uint_as_float(l1);
    } else if (i < 9 * 64 * 32 + 9 * 32 * 32) {   // offset: (tap, oc<32, kk, t)
        int j   = i - 9 * 64 * 32;
        int tap = j / 1024;
        int rem = j - tap * 1024;
        int oc  = rem >> 5;
        int kk  = (rem >> 2) & 7;
        int t   = rem & 3;
        int ci0 = kk * 8 + t;
        float v0 = (oc < 27) ? w_off[(oc * 64 + ci0)     * 9 + tap] : 0.0f;
        float v1 = (oc < 27) ? w_off[(oc * 64 + ci0 + 4) * 9 + tap] : 0.0f;
        uint32_t h0, l0, h1, l1;
        split_tf32(v0, h0, l0);
        split_tf32(v1, h1, l1);
        float* q = g_wOp + (size_t)tap * OC_TAP + kk * OC_SK + t * OC_ST + oc * 4;
        q[0] = __uint_as_float(h0);
        q[1] = __uint_as_float(h1);
        q[2] = __uint_as_float(l0);
        q[3] = __uint_as_float(l1);
    }
}

// ---------------------------------------------------------------------------
// Kernel 1: offset/mask conv as tf32 MMA implicit GEMM (128 thr, quad-B).
// ---------------------------------------------------------------------------
__global__ __launch_bounds__(128, 4) void offset_conv_kernel(
    const float* __restrict__ x,
    const float* __restrict__ b_off)
{
    extern __shared__ float smf[];
    float* As = smf + OC_A;
    float* Bp = smf + OC_BP;

    const int tid  = threadIdx.x;
    const int wid  = tid >> 5;
    const int lid  = tid & 31;
    const int g    = lid >> 2;
    const int t    = lid & 3;
    const int hblk = blockIdx.x;
    const int h    = blockIdx.y;
    const int b    = blockIdx.z;
    const int wo   = hblk * 128 + tid;

    const float* xb = x + (size_t)b * CHI * HW;

    float acc[2][4][4];
    #pragma unroll
    for (int m = 0; m < 2; m++)
        #pragma unroll
        for (int n = 0; n < 4; n++)
            #pragma unroll
            for (int e = 0; e < 4; e++) acc[m][n][e] = 0.0f;

    #pragma unroll 1
    for (int tap = 0; tap < 9; tap++) {
        if (tap) __syncthreads();

        // ---- copy packed B (4352 floats = 1088 float4) ----
        {
            const float4* bs = (const float4*)(g_wOp + (size_t)tap * OC_TAP);
            float4* bd = (float4*)Bp;
            #pragma unroll
            for (int j = 0; j < 9; j++) {
                const int lin = tid + j * 128;
                if (lin < OC_TAP / 4) bd[lin] = bs[lin];
            }
        }

        // ---- A tile: shifted input, zero-padded borders ----
        const int y  = h  - 1 + tap / 3;
        const int xv = wo - 1 + tap % 3;
        const bool valid = (y >= 0) && (y < H_) && (xv >= 0) && (xv < W_);
        const float* xp = xb + y * W_ + xv;
        #pragma unroll
        for (int j = 0; j < 16; j++) {
            float4 v4;
            #pragma unroll
            for (int e = 0; e < 4; e++)
                ((float*)&v4)[e] = valid ? __ldg(xp + (j * 4 + e) * HW) : 0.0f;
            *(float4*)(As + tid * SAS + j * 4) = v4;
        }

        __syncthreads();

        // ---- MMA: 8 k-steps x 4 n-frags x (2m x 3 terms) ----
        #pragma unroll 1
        for (int kk = 0; kk < 8; kk++) {
            const int col = kk * 8 + t;
            uint32_t ah[2][4], al[2][4];
            #pragma unroll
            for (int mi = 0; mi < 2; mi++) {
                const float* ab = As + (wid * 32 + mi * 16 + g) * SAS + col;
                split_tf32(ab[0],           ah[mi][0], al[mi][0]);
                split_tf32(ab[8 * SAS],     ah[mi][1], al[mi][1]);
                split_tf32(ab[4],           ah[mi][2], al[mi][2]);
                split_tf32(ab[8 * SAS + 4], ah[mi][3], al[mi][3]);
            }
            const float* bq_base = Bp + kk * OC_SK + t * OC_ST;
            #pragma unroll
            for (int n = 0; n < 4; n++) {
                const float4 bq = *(const float4*)(bq_base + (n * 8 + g) * 4);
                const uint32_t bh0 = __float_as_uint(bq.x);
                const uint32_t bh1 = __float_as_uint(bq.y);
                const uint32_t bl0 = __float_as_uint(bq.z);
                const uint32_t bl1 = __float_as_uint(bq.w);
                mma8(acc[0][n], ah[0], bh0, bh1);
                mma8(acc[1][n], ah[1], bh0, bh1);
                mma8(acc[0][n], al[0], bh0, bh1);
                mma8(acc[1][n], al[1], bh0, bh1);
                mma8(acc[0][n], ah[0], bl0, bl1);
                mma8(acc[1][n], ah[1], bl0, bl1);
            }
        }
    }

    // ---- epilogue: stage through warp's own A region, write g_om ----
    float* ds = As + wid * 2176;      // [32 oc][34]
    #pragma unroll
    for (int mi = 0; mi < 2; mi++) {
        #pragma unroll
        for (int n = 0; n < 4; n++) {
            const int oc = n * 8 + 2 * t;
            const int p  = mi * 16 + g;
            ds[oc * 34 + p]           = acc[mi][n][0];
            ds[(oc + 1) * 34 + p]     = acc[mi][n][1];
            ds[oc * 34 + p + 8]       = acc[mi][n][2];
            ds[(oc + 1) * 34 + p + 8] = acc[mi][n][3];
        }
    }
    __syncwarp();

    const int pixbase = hblk * 128 + wid * 32;
    #pragma unroll
    for (int oc = 0; oc < 27; oc++) {
        g_om[((size_t)(b * 27 + oc) * H_ + h) * W_ + pixbase + lid] =
            ds[oc * 34 + lid] + __ldg(b_off + oc);
    }
}

// ---------------------------------------------------------------------------
// Kernel 2: deformable conv main GEMM (128 thr, quad-B).
// ---------------------------------------------------------------------------
__global__ __launch_bounds__(128, 3) void dcn_main_kernel(
    const float* __restrict__ x,
    const float* __restrict__ bias,
    float* __restrict__ out)
{
    extern __shared__ float smf[];
    float* As = smf + DM_A;
    float* Bp = smf + DM_BP;

    const int tid  = threadIdx.x;
    const int wid  = tid >> 5;
    const int lid  = tid & 31;
    const int g    = lid >> 2;
    const int t    = lid & 3;
    const int hblk = blockIdx.x;
    const int h    = blockIdx.y;
    const int b    = blockIdx.z;
    const int wo   = hblk * 128 + tid;

    const float* omp = g_om + ((size_t)b * 27 * H_ + h) * W_ + wo;
    const float* xb  = x + (size_t)b * CHI * HW;

    float acc[2][8][4];
    #pragma unroll
    for (int m = 0; m < 2; m++)
        #pragma unroll
        for (int n = 0; n < 8; n++)
            #pragma unroll
            for (int e = 0; e < 4; e++) acc[m][n][e] = 0.0f;

    #pragma unroll 1
    for (int tap = 0; tap < 9; tap++) {
        if (tap) __syncthreads();

        // ---- copy packed B (8448 floats = 2112 float4) ----
        {
            const float4* bs = (const float4*)(g_wBp + (size_t)tap * DM_TAP);
            float4* bd = (float4*)Bp;
            #pragma unroll
            for (int j = 0; j < 17; j++) {
                const int lin = tid + j * 128;
                if (lin < DM_TAP / 4) bd[lin] = bs[lin];
            }
        }

        // ---- sampling params for this thread's pixel ----
        const float oy = omp[(size_t)(2 * tap)     * HW];
        const float ox = omp[(size_t)(2 * tap + 1) * HW];
        const float mz = omp[(size_t)(18 + tap)    * HW];
        const float m  = 1.0f / (1.0f + expf(-mz));

        const float sy = (float)(h  - 1 + tap / 3) + oy;
        const float sx = (float)(wo - 1 + tap % 3) + ox;

        const float y0f = floorf(sy);
        const float x0f = floorf(sx);
        const float dy  = sy - y0f;
        const float dx  = sx - x0f;
        const int y0 = (int)y0f, x0 = (int)x0f;
        const int y1 = y0 + 1,  x1 = x0 + 1;

        const bool vy0 = (y0 >= 0) && (y0 < H_);
        const bool vy1 = (y1 >= 0) && (y1 < H_);
        const bool vx0 = (x0 >= 0) && (x0 < W_);
        const bool vx1 = (x1 >= 0) && (x1 < W_);

        float w00 = (1.0f - dy) * (1.0f - dx) * m;
        float w01 = (1.0f - dy) * dx * m;
        float w10 = dy * (1.0f - dx) * m;
        float w11 = dy * dx * m;
        if (!(vy0 && vx0)) w00 = 0.0f;
        if (!(vy0 && vx1)) w01 = 0.0f;
        if (!(vy1 && vx0)) w10 = 0.0f;
        if (!(vy1 && vx1)) w11 = 0.0f;

        const int cy0 = min(max(y0, 0), H_ - 1);
        const int cy1 = min(max(y1, 0), H_ - 1);
        const int cx0 = min(max(x0, 0), W_ - 1);
        const int cx1 = min(max(x1, 0), W_ - 1);

        const float* p00 = xb + cy0 * W_ + cx0;
        const float* p01 = xb + cy0 * W_ + cx1;
        const float* p10 = xb + cy1 * W_ + cx0;
        const float* p11 = xb + cy1 * W_ + cx1;

        // ---- gather + bilinear: 64 ci for this pixel -> A[tid][ci] ----
        #pragma unroll
        for (int j = 0; j < 16; j++) {
            float4 v4;
            #pragma unroll
            for (int e = 0; e < 4; e++) {
                const int ci = j * 4 + e;
                ((float*)&v4)[e] = w00 * __ldg(p00 + ci * HW)
                                 + w01 * __ldg(p01 + ci * HW)
                                 + w10 * __ldg(p10 + ci * HW)
                                 + w11 * __ldg(p11 + ci * HW);
            }
            *(float4*)(As + tid * SAS + j * 4) = v4;
        }

        __syncthreads();

        // ---- MMA: 8 k-steps x 8 n-frags x (2m x 3 terms) ----
        #pragma unroll 1
        for (int kk = 0; kk < 8; kk++) {
            const int col = kk * 8 + t;
            uint32_t ah[2][4], al[2][4];
            #pragma unroll
            for (int mi = 0; mi < 2; mi++) {
                const float* ab = As + (wid * 32 + mi * 16 + g) * SAS + col;
                split_tf32(ab[0],           ah[mi][0], al[mi][0]);
                split_tf32(ab[8 * SAS],     ah[mi][1], al[mi][1]);
                split_tf32(ab[4],           ah[mi][2], al[mi][2]);
                split_tf32(ab[8 * SAS + 4], ah[mi][3], al[mi][3]);
            }
            const float* bq_base = Bp + kk * DM_SK + t * DM_ST;
            #pragma unroll
            for (int n = 0; n < 8; n++) {
                const float4 bq = *(const float4*)(bq_base + (n * 8 + g) * 4);
                const uint32_t bh0 = __float_as_uint(bq.x);
                const uint32_t bh1 = __float_as_uint(bq.y);
                const uint32_t bl0 = __float_as_uint(bq.z);
                const uint32_t bl1 = __float_as_uint(bq.w);
                mma8(acc[0][n], ah[0], bh0, bh1);
                mma8(acc[1][n], ah[1], bh0, bh1);
                mma8(acc[0][n], al[0], bh0, bh1);
                mma8(acc[1][n], al[1], bh0, bh1);
                mma8(acc[0][n], ah[0], bl0, bl1);
                mma8(acc[1][n], ah[1], bl0, bl1);
            }
        }
    }

    // ---- epilogue: stage D through this warp's own A rows ----
    float* ds = As + wid * 2176;           // [64 co][34] per warp
    #pragma unroll
    for (int mi = 0; mi < 2; mi++) {
        #pragma unroll
        for (int n = 0; n < 8; n++) {
            const int co = n * 8 + 2 * t;
            const int p  = mi * 16 + g;
            ds[co * 34 + p]           = acc[mi][n][0];
            ds[(co + 1) * 34 + p]     = acc[mi][n][1];
            ds[co * 34 + p + 8]       = acc[mi][n][2];
            ds[(co + 1) * 34 + p + 8] = acc[mi][n][3];
        }
    }
    __syncwarp();

    const int pixbase = hblk * 128 + wid * 32;
    #pragma unroll 8
    for (int co = 0; co < 64; co++) {
        out[((size_t)(b * CHO + co) * H_ + h) * W_ + pixbase + lid] =
            ds[co * 34 + lid] + __ldg(bias + co);
    }
}

// ---------------------------------------------------------------------------
extern "C" void kernel_launch(void* const* d_in, const int* in_sizes, int n_in,
                              void* d_out, int out_size)
{
    const float* x      = (const float*)d_in[0];
    const float* w_off  = (const float*)d_in[1];
    const float* b_off  = (const float*)d_in[2];
    const float* weight = (const float*)d_in[3];
    const float* bias   = (const float*)d_in[4];
    float* out = (float*)d_out;

    cudaFuncSetAttribute(offset_conv_kernel,
                         cudaFuncAttributeMaxDynamicSharedMemorySize, OC_TOTAL);
    cudaFuncSetAttribute(dcn_main_kernel,
                         cudaFuncAttributeMaxDynamicSharedMemorySize, DM_TOTAL);

    const int prep_n = 9 * 64 * 32 + 9 * 32 * 32;
    prep_weights_kernel<<<(prep_n + 255) / 256, 256>>>(weight, w_off);
    offset_conv_kernel<<<dim3(2, H_, B_), 128, OC_TOTAL>>>(x, b_off);
    dcn_main_kernel<<<dim3(2, H_, B_), 128, DM_TOTAL>>>(x, bias, out);
}

// round 11
// speedup vs baseline: 1.4711x; 1.3022x over previous
#include <cuda_runtime.h>
#include <cuda_bf16.h>
#include <math.h>
#include <stdint.h>

#define CHI 64
#define CHO 64
#define B_  4
#define H_  128
#define W_  256
#define HW  (H_*W_)

#define AS_U 36                 // A row stride in u32 (32 data + 4 pad)

// packed-B strides (u32). t-block stride ==8 mod 32 -> conflict-free LDS.128
#define DM_ST  264
#define DM_SK  (4*DM_ST)        // 1056 per kk
#define DM_TAP (4*DM_SK)        // 4224 per tap (4 kk)
#define OC_ST  136
#define OC_SK  (4*OC_ST)        // 544
#define OC_TAP (4*OC_SK)        // 2176

// smem layout (u32 offsets): Ah[128][36], Al[128][36], Bp
#define SM_AH  0
#define SM_AL  4608
#define SM_BP  9216
#define DM_TOTAL ((9216 + DM_TAP) * 4)    // 53760 B
#define OC_TOTAL ((9216 + OC_TAP) * 4)    // 45568 B

// scratch: offset/mask conv output [B, 27, H, W]
__device__ float g_om[(size_t)B_ * 27 * H_ * W_];
// quad-packed bf16 hi/lo weights
__device__ uint32_t g_wBp[9 * DM_TAP];
__device__ uint32_t g_wOp[9 * OC_TAP];

// ---------------------------------------------------------------------------
// pack two fp32 (even k, odd k) -> bf16x2 u32 (even in low half)
__device__ __forceinline__ uint32_t pack_bf(float ve, float vo) {
    __nv_bfloat162 h2 = __floats2bfloat162_rn(ve, vo);
    return *reinterpret_cast<uint32_t*>(&h2);
}
// split v-pair into hi bf16x2 and lo bf16x2
__device__ __forceinline__ void split_pair(float ve, float vo,
                                           uint32_t& hp, uint32_t& lp) {
    hp = pack_bf(ve, vo);
    const float fe = __uint_as_float(hp << 16);
    const float fo = __uint_as_float(hp & 0xFFFF0000u);
    lp = pack_bf(ve - fe, vo - fo);
}
__device__ __forceinline__ void mmabf(float* d, const uint32_t* a,
                                      uint32_t b0, uint32_t b1) {
    asm volatile(
        "mma.sync.aligned.m16n8k16.row.col.f32.bf16.bf16.f32 "
        "{%0,%1,%2,%3}, {%4,%5,%6,%7}, {%8,%9}, {%0,%1,%2,%3};"
        : "+f"(d[0]), "+f"(d[1]), "+f"(d[2]), "+f"(d[3])
        : "r"(a[0]), "r"(a[1]), "r"(a[2]), "r"(a[3]), "r"(b0), "r"(b1));
}

// ---------------------------------------------------------------------------
// prep: quad-packed bf16 hi/lo weight images.
// quad(tap,kk,t,co) = {bh(k=2t), bh(k=2t+8), bl(k=2t), bl(k=2t+8)} pairs
// ---------------------------------------------------------------------------
__global__ void prep_weights_kernel(const float* __restrict__ w,
                                    const float* __restrict__ w_off)
{
    int i = blockIdx.x * 256 + threadIdx.x;
    if (i < 9 * 64 * 16) {                        // main: (tap, co, kk, t)
        int tap = i / 1024;
        int rem = i - tap * 1024;
        int co  = rem >> 4;
        int kk  = (rem >> 2) & 3;
        int t   = rem & 3;
        int c0  = kk * 16 + 2 * t;
        float v0 = w[(co * 64 + c0)     * 9 + tap];
        float v1 = w[(co * 64 + c0 + 1) * 9 + tap];
        float v8 = w[(co * 64 + c0 + 8) * 9 + tap];
        float v9 = w[(co * 64 + c0 + 9) * 9 + tap];
        uint32_t h0, l0, h8, l8;
        split_pair(v0, v1, h0, l0);
        split_pair(v8, v9, h8, l8);
        uint32_t* q = g_wBp + (size_t)tap * DM_TAP + kk * DM_SK + t * DM_ST + co * 4;
        q[0] = h0; q[1] = h8; q[2] = l0; q[3] = l8;
    } else if (i < 9 * 64 * 16 + 9 * 32 * 16) {   // offset: (tap, oc<32, kk, t)
        int j   = i - 9 * 64 * 16;
        int tap = j / 512;
        int rem = j - tap * 512;
        int oc  = rem >> 4;
        int kk  = (rem >> 2) & 3;
        int t   = rem & 3;
        int c0  = kk * 16 + 2 * t;
        float v0 = (oc < 27) ? w_off[(oc * 64 + c0)     * 9 + tap] : 0.0f;
        float v1 = (oc < 27) ? w_off[(oc * 64 + c0 + 1) * 9 + tap] : 0.0f;
        float v8 = (oc < 27) ? w_off[(oc * 64 + c0 + 8) * 9 + tap] : 0.0f;
        float v9 = (oc < 27) ? w_off[(oc * 64 + c0 + 9) * 9 + tap] : 0.0f;
        uint32_t h0, l0, h8, l8;
        split_pair(v0, v1, h0, l0);
        split_pair(v8, v9, h8, l8);
        uint32_t* q = g_wOp + (size_t)tap * OC_TAP + kk * OC_SK + t * OC_ST + oc * 4;
        q[0] = h0; q[1] = h8; q[2] = l0; q[3] = l8;
    }
}

// ---------------------------------------------------------------------------
// Kernel 1: offset/mask conv, bf16 3-term MMA implicit GEMM (128 thr).
// ---------------------------------------------------------------------------
__global__ __launch_bounds__(128, 4) void offset_conv_kernel(
    const float* __restrict__ x,
    const float* __restrict__ b_off)
{
    extern __shared__ uint32_t smu[];
    uint32_t* Ah = smu + SM_AH;
    uint32_t* Al = smu + SM_AL;
    uint32_t* Bp = smu + SM_BP;

    const int tid  = threadIdx.x;
    const int wid  = tid >> 5;
    const int lid  = tid & 31;
    const int g    = lid >> 2;
    const int t    = lid & 3;
    const int hblk = blockIdx.x;
    const int h    = blockIdx.y;
    const int b    = blockIdx.z;
    const int wo   = hblk * 128 + tid;

    const float* xb = x + (size_t)b * CHI * HW;

    float acc[2][4][4];
    #pragma unroll
    for (int m = 0; m < 2; m++)
        #pragma unroll
        for (int n = 0; n < 4; n++)
            #pragma unroll
            for (int e = 0; e < 4; e++) acc[m][n][e] = 0.0f;

    #pragma unroll 1
    for (int tap = 0; tap < 9; tap++) {
        if (tap) __syncthreads();

        // ---- copy packed B (2176 u32 = 544 uint4) ----
        {
            const uint4* bs = (const uint4*)(g_wOp + (size_t)tap * OC_TAP);
            uint4* bd = (uint4*)Bp;
            #pragma unroll
            for (int j = 0; j < 5; j++) {
                const int lin = tid + j * 128;
                if (lin < OC_TAP / 4) bd[lin] = bs[lin];
            }
        }

        // ---- A tile: shifted input, bf16 hi/lo split at load ----
        const int y  = h  - 1 + tap / 3;
        const int xv = wo - 1 + tap % 3;
        const bool valid = (y >= 0) && (y < H_) && (xv >= 0) && (xv < W_);
        const float* xp = xb + y * W_ + xv;
        #pragma unroll
        for (int j2 = 0; j2 < 8; j2++) {
            float v[8];
            #pragma unroll
            for (int e = 0; e < 8; e++)
                v[e] = valid ? __ldg(xp + (j2 * 8 + e) * HW) : 0.0f;
            uint4 hq, lq;
            split_pair(v[0], v[1], hq.x, lq.x);
            split_pair(v[2], v[3], hq.y, lq.y);
            split_pair(v[4], v[5], hq.z, lq.z);
            split_pair(v[6], v[7], hq.w, lq.w);
            *(uint4*)(Ah + tid * AS_U + j2 * 4) = hq;
            *(uint4*)(Al + tid * AS_U + j2 * 4) = lq;
        }

        __syncthreads();

        // ---- MMA: 4 k16-steps x 4 n-frags x (2m x 3 terms) ----
        #pragma unroll
        for (int kk = 0; kk < 4; kk++) {
            uint32_t ah[2][4], al[2][4];
            #pragma unroll
            for (int mi = 0; mi < 2; mi++) {
                const int base = (wid * 32 + mi * 16 + g) * AS_U + kk * 8 + t;
                ah[mi][0] = Ah[base];
                ah[mi][1] = Ah[base + 8 * AS_U];
                ah[mi][2] = Ah[base + 4];
                ah[mi][3] = Ah[base + 8 * AS_U + 4];
                al[mi][0] = Al[base];
                al[mi][1] = Al[base + 8 * AS_U];
                al[mi][2] = Al[base + 4];
                al[mi][3] = Al[base + 8 * AS_U + 4];
            }
            const uint32_t* bq_base = Bp + kk * OC_SK + t * OC_ST;
            #pragma unroll
            for (int n = 0; n < 4; n++) {
                const uint4 bq = *(const uint4*)(bq_base + (n * 8 + g) * 4);
                mmabf(acc[0][n], ah[0], bq.x, bq.y);
                mmabf(acc[1][n], ah[1], bq.x, bq.y);
                mmabf(acc[0][n], al[0], bq.x, bq.y);
                mmabf(acc[1][n], al[1], bq.x, bq.y);
                mmabf(acc[0][n], ah[0], bq.z, bq.w);
                mmabf(acc[1][n], ah[1], bq.z, bq.w);
            }
        }
    }

    // ---- epilogue: stage via smem (barrier: A no longer needed) ----
    __syncthreads();
    float* ds = (float*)smu + wid * 2176;      // [32 oc][34]
    #pragma unroll
    for (int mi = 0; mi < 2; mi++) {
        #pragma unroll
        for (int n = 0; n < 4; n++) {
            const int oc = n * 8 + 2 * t;
            const int p  = mi * 16 + g;
            ds[oc * 34 + p]           = acc[mi][n][0];
            ds[(oc + 1) * 34 + p]     = acc[mi][n][1];
            ds[oc * 34 + p + 8]       = acc[mi][n][2];
            ds[(oc + 1) * 34 + p + 8] = acc[mi][n][3];
        }
    }
    __syncwarp();

    const int pixbase = hblk * 128 + wid * 32;
    #pragma unroll
    for (int oc = 0; oc < 27; oc++) {
        g_om[((size_t)(b * 27 + oc) * H_ + h) * W_ + pixbase + lid] =
            ds[oc * 34 + lid] + __ldg(b_off + oc);
    }
}

// ---------------------------------------------------------------------------
// Kernel 2: deformable conv main GEMM, bf16 3-term (128 thr).
// ---------------------------------------------------------------------------
__global__ __launch_bounds__(128, 4) void dcn_main_kernel(
    const float* __restrict__ x,
    const float* __restrict__ bias,
    float* __restrict__ out)
{
    extern __shared__ uint32_t smu[];
    uint32_t* Ah = smu + SM_AH;
    uint32_t* Al = smu + SM_AL;
    uint32_t* Bp = smu + SM_BP;

    const int tid  = threadIdx.x;
    const int wid  = tid >> 5;
    const int lid  = tid & 31;
    const int g    = lid >> 2;
    const int t    = lid & 3;
    const int hblk = blockIdx.x;
    const int h    = blockIdx.y;
    const int b    = blockIdx.z;
    const int wo   = hblk * 128 + tid;

    const float* omp = g_om + ((size_t)b * 27 * H_ + h) * W_ + wo;
    const float* xb  = x + (size_t)b * CHI * HW;

    float acc[2][8][4];
    #pragma unroll
    for (int m = 0; m < 2; m++)
        #pragma unroll
        for (int n = 0; n < 8; n++)
            #pragma unroll
            for (int e = 0; e < 4; e++) acc[m][n][e] = 0.0f;

    #pragma unroll 1
    for (int tap = 0; tap < 9; tap++) {
        if (tap) __syncthreads();

        // ---- copy packed B (4224 u32 = 1056 uint4) ----
        {
            const uint4* bs = (const uint4*)(g_wBp + (size_t)tap * DM_TAP);
            uint4* bd = (uint4*)Bp;
            #pragma unroll
            for (int j = 0; j < 9; j++) {
                const int lin = tid + j * 128;
                if (lin < DM_TAP / 4) bd[lin] = bs[lin];
            }
        }

        // ---- sampling params for this thread's pixel ----
        const float oy = omp[(size_t)(2 * tap)     * HW];
        const float ox = omp[(size_t)(2 * tap + 1) * HW];
        const float mz = omp[(size_t)(18 + tap)    * HW];
        const float m  = 1.0f / (1.0f + expf(-mz));

        const float sy = (float)(h  - 1 + tap / 3) + oy;
        const float sx = (float)(wo - 1 + tap % 3) + ox;

        const float y0f = floorf(sy);
        const float x0f = floorf(sx);
        const float dy  = sy - y0f;
        const float dx  = sx - x0f;
        const int y0 = (int)y0f, x0 = (int)x0f;
        const int y1 = y0 + 1,  x1 = x0 + 1;

        const bool vy0 = (y0 >= 0) && (y0 < H_);
        const bool vy1 = (y1 >= 0) && (y1 < H_);
        const bool vx0 = (x0 >= 0) && (x0 < W_);
        const bool vx1 = (x1 >= 0) && (x1 < W_);

        float w00 = (1.0f - dy) * (1.0f - dx) * m;
        float w01 = (1.0f - dy) * dx * m;
        float w10 = dy * (1.0f - dx) * m;
        float w11 = dy * dx * m;
        if (!(vy0 && vx0)) w00 = 0.0f;
        if (!(vy0 && vx1)) w01 = 0.0f;
        if (!(vy1 && vx0)) w10 = 0.0f;
        if (!(vy1 && vx1)) w11 = 0.0f;

        const int cy0 = min(max(y0, 0), H_ - 1);
        const int cy1 = min(max(y1, 0), H_ - 1);
        const int cx0 = min(max(x0, 0), W_ - 1);
        const int cx1 = min(max(x1, 0), W_ - 1);

        const float* p00 = xb + cy0 * W_ + cx0;
        const float* p01 = xb + cy0 * W_ + cx1;
        const float* p10 = xb + cy1 * W_ + cx0;
        const float* p11 = xb + cy1 * W_ + cx1;

        // ---- gather + bilinear + bf16 split: 64 ci -> Ah/Al[tid] ----
        #pragma unroll
        for (int j2 = 0; j2 < 8; j2++) {
            float v[8];
            #pragma unroll
            for (int e = 0; e < 8; e++) {
                const int ci = j2 * 8 + e;
                v[e] = w00 * __ldg(p00 + ci * HW)
                     + w01 * __ldg(p01 + ci * HW)
                     + w10 * __ldg(p10 + ci * HW)
                     + w11 * __ldg(p11 + ci * HW);
            }
            uint4 hq, lq;
            split_pair(v[0], v[1], hq.x, lq.x);
            split_pair(v[2], v[3], hq.y, lq.y);
            split_pair(v[4], v[5], hq.z, lq.z);
            split_pair(v[6], v[7], hq.w, lq.w);
            *(uint4*)(Ah + tid * AS_U + j2 * 4) = hq;
            *(uint4*)(Al + tid * AS_U + j2 * 4) = lq;
        }

        __syncthreads();

        // ---- MMA: 4 k16-steps x 8 n-frags x (2m x 3 terms) ----
        #pragma unroll
        for (int kk = 0; kk < 4; kk++) {
            uint32_t ah[2][4], al[2][4];
            #pragma unroll
            for (int mi = 0; mi < 2; mi++) {
                const int base = (wid * 32 + mi * 16 + g) * AS_U + kk * 8 + t;
                ah[mi][0] = Ah[base];
                ah[mi][1] = Ah[base + 8 * AS_U];
                ah[mi][2] = Ah[base + 4];
                ah[mi][3] = Ah[base + 8 * AS_U + 4];
                al[mi][0] = Al[base];
                al[mi][1] = Al[base + 8 * AS_U];
                al[mi][2] = Al[base + 4];
                al[mi][3] = Al[base + 8 * AS_U + 4];
            }
            const uint32_t* bq_base = Bp + kk * DM_SK + t * DM_ST;
            #pragma unroll
            for (int n = 0; n < 8; n++) {
                const uint4 bq = *(const uint4*)(bq_base + (n * 8 + g) * 4);
                mmabf(acc[0][n], ah[0], bq.x, bq.y);
                mmabf(acc[1][n], ah[1], bq.x, bq.y);
                mmabf(acc[0][n], al[0], bq.x, bq.y);
                mmabf(acc[1][n], al[1], bq.x, bq.y);
                mmabf(acc[0][n], ah[0], bq.z, bq.w);
                mmabf(acc[1][n], ah[1], bq.z, bq.w);
            }
        }
    }

    // ---- epilogue: stage via smem (barrier: A no longer needed) ----
    __syncthreads();
    float* ds = (float*)smu + wid * 2176;      // [64 co][34] per warp
    #pragma unroll
    for (int mi = 0; mi < 2; mi++) {
        #pragma unroll
        for (int n = 0; n < 8; n++) {
            const int co = n * 8 + 2 * t;
            const int p  = mi * 16 + g;
            ds[co * 34 + p]           = acc[mi][n][0];
            ds[(co + 1) * 34 + p]     = acc[mi][n][1];
            ds[co * 34 + p + 8]       = acc[mi][n][2];
            ds[(co + 1) * 34 + p + 8] = acc[mi][n][3];
        }
    }
    __syncwarp();

    const int pixbase = hblk * 128 + wid * 32;
    #pragma unroll 8
    for (int co = 0; co < 64; co++) {
        out[((size_t)(b * CHO + co) * H_ + h) * W_ + pixbase + lid] =
            ds[co * 34 + lid] + __ldg(bias + co);
    }
}

// ---------------------------------------------------------------------------
extern "C" void kernel_launch(void* const* d_in, const int* in_sizes, int n_in,
                              void* d_out, int out_size)
{
    const float* x      = (const float*)d_in[0];
    const float* w_off  = (const float*)d_in[1];
    const float* b_off  = (const float*)d_in[2];
    const float* weight = (const float*)d_in[3];
    const float* bias   = (const float*)d_in[4];
    float* out = (float*)d_out;

    cudaFuncSetAttribute(offset_conv_kernel,
                         cudaFuncAttributeMaxDynamicSharedMemorySize, OC_TOTAL);
    cudaFuncSetAttribute(dcn_main_kernel,
                         cudaFuncAttributeMaxDynamicSharedMemorySize, DM_TOTAL);

    const int prep_n = 9 * 64 * 16 + 9 * 32 * 16;
    prep_weights_kernel<<<(prep_n + 255) / 256, 256>>>(weight, w_off);
    offset_conv_kernel<<<dim3(2, H_, B_), 128, OC_TOTAL>>>(x, b_off);
    dcn_main_kernel<<<dim3(2, H_, B_), 128, DM_TOTAL>>>(x, bias, out);
}

// round 12
// speedup vs baseline: 1.4722x; 1.0008x over previous
#include <cuda_runtime.h>
#include <cuda_bf16.h>
#include <math.h>
#include <stdint.h>

#define CHI 64
#define CHO 64
#define B_  4
#define H_  128
#define W_  256
#define HW  (H_*W_)

#define AS_U 36                 // A row stride in u32 (32 data + 4 pad)

// packed-B strides (u32). t-block stride ==8 mod 32 -> conflict-free LDS.128
#define DM_ST  264
#define DM_SK  (4*DM_ST)        // 1056 per kk
#define DM_TAP (4*DM_SK)        // 4224 per tap (4 kk)
#define OC_ST  136
#define OC_SK  (4*OC_ST)        // 544
#define OC_TAP (4*OC_SK)        // 2176

// smem layout (u32 offsets): Ah[128][36], Al[128][36], Bp
#define SM_AH  0
#define SM_AL  4608
#define SM_BP  9216
#define DM_TOTAL ((9216 + DM_TAP) * 4)    // 53760 B
#define OC_TOTAL ((9216 + OC_TAP) * 4)    // 45568 B

// scratch: offset/mask conv output [B, 27, H, W]
__device__ float g_om[(size_t)B_ * 27 * H_ * W_];
// quad-packed bf16 hi/lo weights
__device__ uint32_t g_wBp[9 * DM_TAP];
__device__ uint32_t g_wOp[9 * OC_TAP];

// ---------------------------------------------------------------------------
// pack two fp32 (even k, odd k) -> bf16x2 u32 (even in low half)
__device__ __forceinline__ uint32_t pack_bf(float ve, float vo) {
    __nv_bfloat162 h2 = __floats2bfloat162_rn(ve, vo);
    return *reinterpret_cast<uint32_t*>(&h2);
}
// split v-pair into hi bf16x2 and lo bf16x2
__device__ __forceinline__ void split_pair(float ve, float vo,
                                           uint32_t& hp, uint32_t& lp) {
    hp = pack_bf(ve, vo);
    const float fe = __uint_as_float(hp << 16);
    const float fo = __uint_as_float(hp & 0xFFFF0000u);
    lp = pack_bf(ve - fe, vo - fo);
}
__device__ __forceinline__ void mmabf(float* d, const uint32_t* a,
                                      uint32_t b0, uint32_t b1) {
    asm volatile(
        "mma.sync.aligned.m16n8k16.row.col.f32.bf16.bf16.f32 "
        "{%0,%1,%2,%3}, {%4,%5,%6,%7}, {%8,%9}, {%0,%1,%2,%3};"
        : "+f"(d[0]), "+f"(d[1]), "+f"(d[2]), "+f"(d[3])
        : "r"(a[0]), "r"(a[1]), "r"(a[2]), "r"(a[3]), "r"(b0), "r"(b1));
}

// ---------------------------------------------------------------------------
// prep: quad-packed bf16 hi/lo weight images.
// quad(tap,kk,t,co) = {bh(k=2t), bh(k=2t+8), bl(k=2t), bl(k=2t+8)} pairs
// ---------------------------------------------------------------------------
__global__ void prep_weights_kernel(const float* __restrict__ w,
                                    const float* __restrict__ w_off)
{
    int i = blockIdx.x * 256 + threadIdx.x;
    if (i < 9 * 64 * 16) {                        // main: (tap, co, kk, t)
        int tap = i / 1024;
        int rem = i - tap * 1024;
        int co  = rem >> 4;
        int kk  = (rem >> 2) & 3;
        int t   = rem & 3;
        int c0  = kk * 16 + 2 * t;
        float v0 = w[(co * 64 + c0)     * 9 + tap];
        float v1 = w[(co * 64 + c0 + 1) * 9 + tap];
        float v8 = w[(co * 64 + c0 + 8) * 9 + tap];
        float v9 = w[(co * 64 + c0 + 9) * 9 + tap];
        uint32_t h0, l0, h8, l8;
        split_pair(v0, v1, h0, l0);
        split_pair(v8, v9, h8, l8);
        uint32_t* q = g_wBp + (size_t)tap * DM_TAP + kk * DM_SK + t * DM_ST + co * 4;
        q[0] = h0; q[1] = h8; q[2] = l0; q[3] = l8;
    } else if (i < 9 * 64 * 16 + 9 * 32 * 16) {   // offset: (tap, oc<32, kk, t)
        int j   = i - 9 * 64 * 16;
        int tap = j / 512;
        int rem = j - tap * 512;
        int oc  = rem >> 4;
        int kk  = (rem >> 2) & 3;
        int t   = rem & 3;
        int c0  = kk * 16 + 2 * t;
        float v0 = (oc < 27) ? w_off[(oc * 64 + c0)     * 9 + tap] : 0.0f;
        float v1 = (oc < 27) ? w_off[(oc * 64 + c0 + 1) * 9 + tap] : 0.0f;
        float v8 = (oc < 27) ? w_off[(oc * 64 + c0 + 8) * 9 + tap] : 0.0f;
        float v9 = (oc < 27) ? w_off[(oc * 64 + c0 + 9) * 9 + tap] : 0.0f;
        uint32_t h0, l0, h8, l8;
        split_pair(v0, v1, h0, l0);
        split_pair(v8, v9, h8, l8);
        uint32_t* q = g_wOp + (size_t)tap * OC_TAP + kk * OC_SK + t * OC_ST + oc * 4;
        q[0] = h0; q[1] = h8; q[2] = l0; q[3] = l8;
    }
}

// ---------------------------------------------------------------------------
// Kernel 1: offset/mask conv, bf16 3-term MMA implicit GEMM (128 thr).
// ---------------------------------------------------------------------------
__global__ __launch_bounds__(128, 4) void offset_conv_kernel(
    const float* __restrict__ x,
    const float* __restrict__ b_off)
{
    extern __shared__ uint32_t smu[];
    uint32_t* Ah = smu + SM_AH;
    uint32_t* Al = smu + SM_AL;
    uint32_t* Bp = smu + SM_BP;

    const int tid  = threadIdx.x;
    const int wid  = tid >> 5;
    const int lid  = tid & 31;
    const int g    = lid >> 2;
    const int t    = lid & 3;
    const int hblk = blockIdx.x;
    const int h    = blockIdx.y;
    const int b    = blockIdx.z;
    const int wo   = hblk * 128 + tid;

    const float* xb = x + (size_t)b * CHI * HW;

    float acc[2][4][4];
    #pragma unroll
    for (int m = 0; m < 2; m++)
        #pragma unroll
        for (int n = 0; n < 4; n++)
            #pragma unroll
            for (int e = 0; e < 4; e++) acc[m][n][e] = 0.0f;

    #pragma unroll 1
    for (int tap = 0; tap < 9; tap++) {
        if (tap) __syncthreads();

        // ---- copy packed B (2176 u32 = 544 uint4) ----
        {
            const uint4* bs = (const uint4*)(g_wOp + (size_t)tap * OC_TAP);
            uint4* bd = (uint4*)Bp;
            #pragma unroll
            for (int j = 0; j < 5; j++) {
                const int lin = tid + j * 128;
                if (lin < OC_TAP / 4) bd[lin] = bs[lin];
            }
        }

        // ---- A tile: shifted input, bf16 hi/lo split at load ----
        const int y  = h  - 1 + tap / 3;
        const int xv = wo - 1 + tap % 3;
        const bool valid = (y >= 0) && (y < H_) && (xv >= 0) && (xv < W_);
        const float* xp = xb + y * W_ + xv;
        #pragma unroll
        for (int j2 = 0; j2 < 8; j2++) {
            float v[8];
            #pragma unroll
            for (int e = 0; e < 8; e++)
                v[e] = valid ? __ldg(xp + (j2 * 8 + e) * HW) : 0.0f;
            uint4 hq, lq;
            split_pair(v[0], v[1], hq.x, lq.x);
            split_pair(v[2], v[3], hq.y, lq.y);
            split_pair(v[4], v[5], hq.z, lq.z);
            split_pair(v[6], v[7], hq.w, lq.w);
            *(uint4*)(Ah + tid * AS_U + j2 * 4) = hq;
            *(uint4*)(Al + tid * AS_U + j2 * 4) = lq;
        }

        __syncthreads();

        // ---- MMA: 4 k16-steps x 4 n-frags x (2m x 3 terms) ----
        #pragma unroll
        for (int kk = 0; kk < 4; kk++) {
            uint32_t ah[2][4], al[2][4];
            #pragma unroll
            for (int mi = 0; mi < 2; mi++) {
                const int base = (wid * 32 + mi * 16 + g) * AS_U + kk * 8 + t;
                ah[mi][0] = Ah[base];
                ah[mi][1] = Ah[base + 8 * AS_U];
                ah[mi][2] = Ah[base + 4];
                ah[mi][3] = Ah[base + 8 * AS_U + 4];
                al[mi][0] = Al[base];
                al[mi][1] = Al[base + 8 * AS_U];
                al[mi][2] = Al[base + 4];
                al[mi][3] = Al[base + 8 * AS_U + 4];
            }
            const uint32_t* bq_base = Bp + kk * OC_SK + t * OC_ST;
            #pragma unroll
            for (int n = 0; n < 4; n++) {
                const uint4 bq = *(const uint4*)(bq_base + (n * 8 + g) * 4);
                mmabf(acc[0][n], ah[0], bq.x, bq.y);
                mmabf(acc[1][n], ah[1], bq.x, bq.y);
                mmabf(acc[0][n], al[0], bq.x, bq.y);
                mmabf(acc[1][n], al[1], bq.x, bq.y);
                mmabf(acc[0][n], ah[0], bq.z, bq.w);
                mmabf(acc[1][n], ah[1], bq.z, bq.w);
            }
        }
    }

    // ---- epilogue: stage via smem (barrier: A no longer needed) ----
    __syncthreads();
    float* ds = (float*)smu + wid * 2176;      // [32 oc][34]
    #pragma unroll
    for (int mi = 0; mi < 2; mi++) {
        #pragma unroll
        for (int n = 0; n < 4; n++) {
            const int oc = n * 8 + 2 * t;
            const int p  = mi * 16 + g;
            ds[oc * 34 + p]           = acc[mi][n][0];
            ds[(oc + 1) * 34 + p]     = acc[mi][n][1];
            ds[oc * 34 + p + 8]       = acc[mi][n][2];
            ds[(oc + 1) * 34 + p + 8] = acc[mi][n][3];
        }
    }
    __syncwarp();

    const int pixbase = hblk * 128 + wid * 32;
    #pragma unroll
    for (int oc = 0; oc < 27; oc++) {
        g_om[((size_t)(b * 27 + oc) * H_ + h) * W_ + pixbase + lid] =
            ds[oc * 34 + lid] + __ldg(b_off + oc);
    }
}

// ---------------------------------------------------------------------------
// Kernel 2: deformable conv main GEMM, bf16 3-term (128 thr).
// ---------------------------------------------------------------------------
__global__ __launch_bounds__(128, 4) void dcn_main_kernel(
    const float* __restrict__ x,
    const float* __restrict__ bias,
    float* __restrict__ out)
{
    extern __shared__ uint32_t smu[];
    uint32_t* Ah = smu + SM_AH;
    uint32_t* Al = smu + SM_AL;
    uint32_t* Bp = smu + SM_BP;

    const int tid  = threadIdx.x;
    const int wid  = tid >> 5;
    const int lid  = tid & 31;
    const int g    = lid >> 2;
    const int t    = lid & 3;
    const int hblk = blockIdx.x;
    const int h    = blockIdx.y;
    const int b    = blockIdx.z;
    const int wo   = hblk * 128 + tid;

    const float* omp = g_om + ((size_t)b * 27 * H_ + h) * W_ + wo;
    const float* xb  = x + (size_t)b * CHI * HW;

    float acc[2][8][4];
    #pragma unroll
    for (int m = 0; m < 2; m++)
        #pragma unroll
        for (int n = 0; n < 8; n++)
            #pragma unroll
            for (int e = 0; e < 4; e++) acc[m][n][e] = 0.0f;

    #pragma unroll 1
    for (int tap = 0; tap < 9; tap++) {
        if (tap) __syncthreads();

        // ---- copy packed B (4224 u32 = 1056 uint4) ----
        {
            const uint4* bs = (const uint4*)(g_wBp + (size_t)tap * DM_TAP);
            uint4* bd = (uint4*)Bp;
            #pragma unroll
            for (int j = 0; j < 9; j++) {
                const int lin = tid + j * 128;
                if (lin < DM_TAP / 4) bd[lin] = bs[lin];
            }
        }

        // ---- sampling params for this thread's pixel ----
        const float oy = omp[(size_t)(2 * tap)     * HW];
        const float ox = omp[(size_t)(2 * tap + 1) * HW];
        const float mz = omp[(size_t)(18 + tap)    * HW];
        const float m  = 1.0f / (1.0f + expf(-mz));

        const float sy = (float)(h  - 1 + tap / 3) + oy;
        const float sx = (float)(wo - 1 + tap % 3) + ox;

        const float y0f = floorf(sy);
        const float x0f = floorf(sx);
        const float dy  = sy - y0f;
        const float dx  = sx - x0f;
        const int y0 = (int)y0f, x0 = (int)x0f;
        const int y1 = y0 + 1,  x1 = x0 + 1;

        const bool vy0 = (y0 >= 0) && (y0 < H_);
        const bool vy1 = (y1 >= 0) && (y1 < H_);
        const bool vx0 = (x0 >= 0) && (x0 < W_);
        const bool vx1 = (x1 >= 0) && (x1 < W_);

        float w00 = (1.0f - dy) * (1.0f - dx) * m;
        float w01 = (1.0f - dy) * dx * m;
        float w10 = dy * (1.0f - dx) * m;
        float w11 = dy * dx * m;
        if (!(vy0 && vx0)) w00 = 0.0f;
        if (!(vy0 && vx1)) w01 = 0.0f;
        if (!(vy1 && vx0)) w10 = 0.0f;
        if (!(vy1 && vx1)) w11 = 0.0f;

        const int cy0 = min(max(y0, 0), H_ - 1);
        const int cy1 = min(max(y1, 0), H_ - 1);
        const int cx0 = min(max(x0, 0), W_ - 1);
        const int cx1 = min(max(x1, 0), W_ - 1);

        const float* p00 = xb + cy0 * W_ + cx0;
        const float* p01 = xb + cy0 * W_ + cx1;
        const float* p10 = xb + cy1 * W_ + cx0;
        const float* p11 = xb + cy1 * W_ + cx1;

        // ---- gather + bilinear + bf16 split: 64 ci -> Ah/Al[tid] ----
        #pragma unroll
        for (int j2 = 0; j2 < 8; j2++) {
            float v[8];
            #pragma unroll
            for (int e = 0; e < 8; e++) {
                const int ci = j2 * 8 + e;
                v[e] = w00 * __ldg(p00 + ci * HW)
                     + w01 * __ldg(p01 + ci * HW)
                     + w10 * __ldg(p10 + ci * HW)
                     + w11 * __ldg(p11 + ci * HW);
            }
            uint4 hq, lq;
            split_pair(v[0], v[1], hq.x, lq.x);
            split_pair(v[2], v[3], hq.y, lq.y);
            split_pair(v[4], v[5], hq.z, lq.z);
            split_pair(v[6], v[7], hq.w, lq.w);
            *(uint4*)(Ah + tid * AS_U + j2 * 4) = hq;
            *(uint4*)(Al + tid * AS_U + j2 * 4) = lq;
        }

        __syncthreads();

        // ---- MMA: 4 k16-steps x 8 n-frags x (2m x 3 terms) ----
        #pragma unroll
        for (int kk = 0; kk < 4; kk++) {
            uint32_t ah[2][4], al[2][4];
            #pragma unroll
            for (int mi = 0; mi < 2; mi++) {
                const int base = (wid * 32 + mi * 16 + g) * AS_U + kk * 8 + t;
                ah[mi][0] = Ah[base];
                ah[mi][1] = Ah[base + 8 * AS_U];
                ah[mi][2] = Ah[base + 4];
                ah[mi][3] = Ah[base + 8 * AS_U + 4];
                al[mi][0] = Al[base];
                al[mi][1] = Al[base + 8 * AS_U];
                al[mi][2] = Al[base + 4];
                al[mi][3] = Al[base + 8 * AS_U + 4];
            }
            const uint32_t* bq_base = Bp + kk * DM_SK + t * DM_ST;
            #pragma unroll
            for (int n = 0; n < 8; n++) {
                const uint4 bq = *(const uint4*)(bq_base + (n * 8 + g) * 4);
                mmabf(acc[0][n], ah[0], bq.x, bq.y);
                mmabf(acc[1][n], ah[1], bq.x, bq.y);
                mmabf(acc[0][n], al[0], bq.x, bq.y);
                mmabf(acc[1][n], al[1], bq.x, bq.y);
                mmabf(acc[0][n], ah[0], bq.z, bq.w);
                mmabf(acc[1][n], ah[1], bq.z, bq.w);
            }
        }
    }

    // ---- epilogue: stage via smem (barrier: A no longer needed) ----
    __syncthreads();
    float* ds = (float*)smu + wid * 2176;      // [64 co][34] per warp
    #pragma unroll
    for (int mi = 0; mi < 2; mi++) {
        #pragma unroll
        for (int n = 0; n < 8; n++) {
            const int co = n * 8 + 2 * t;
            const int p  = mi * 16 + g;
            ds[co * 34 + p]           = acc[mi][n][0];
            ds[(co + 1) * 34 + p]     = acc[mi][n][1];
            ds[co * 34 + p + 8]       = acc[mi][n][2];
            ds[(co + 1) * 34 + p + 8] = acc[mi][n][3];
        }
    }
    __syncwarp();

    const int pixbase = hblk * 128 + wid * 32;
    #pragma unroll 8
    for (int co = 0; co < 64; co++) {
        out[((size_t)(b * CHO + co) * H_ + h) * W_ + pixbase + lid] =
            ds[co * 34 + lid] + __ldg(bias + co);
    }
}

// ---------------------------------------------------------------------------
extern "C" void kernel_launch(void* const* d_in, const int* in_sizes, int n_in,
                              void* d_out, int out_size)
{
    const float* x      = (const float*)d_in[0];
    const float* w_off  = (const float*)d_in[1];
    const float* b_off  = (const float*)d_in[2];
    const float* weight = (const float*)d_in[3];
    const float* bias   = (const float*)d_in[4];
    float* out = (float*)d_out;

    cudaFuncSetAttribute(offset_conv_kernel,
                         cudaFuncAttributeMaxDynamicSharedMemorySize, OC_TOTAL);
    cudaFuncSetAttribute(dcn_main_kernel,
                         cudaFuncAttributeMaxDynamicSharedMemorySize, DM_TOTAL);

    const int prep_n = 9 * 64 * 16 + 9 * 32 * 16;
    prep_weights_kernel<<<(prep_n + 255) / 256, 256>>>(weight, w_off);
    offset_conv_kernel<<<dim3(2, H_, B_), 128, OC_TOTAL>>>(x, b_off);
    dcn_main_kernel<<<dim3(2, H_, B_), 128, DM_TOTAL>>>(x, bias, out);
}

// round 13
// speedup vs baseline: 1.6118x; 1.0948x over previous
#include <cuda_runtime.h>
#include <cuda_bf16.h>
#include <math.h>
#include <stdint.h>

#define CHI 64
#define CHO 64
#define B_  4
#define H_  128
#define W_  256
#define HW  (H_*W_)

#define AS_U 36                 // A row stride in u32 (32 data + 4 pad)

// packed-B strides (u32). t-block stride ==8 mod 32 -> conflict-free LDS.128
#define DM_ST  264
#define DM_SK  (4*DM_ST)        // 1056 per kk
#define DM_TAP (4*DM_SK)        // 4224 per tap (4 kk)
#define OC_ST  136
#define OC_SK  (4*OC_ST)        // 544
#define OC_TAP (4*OC_SK)        // 2176

// fused smem layout (u32 offsets): Ah[128][36], Al[128][36], Bp, om[128][27]
#define SM_AH  0
#define SM_AL  4608
#define SM_BP  9216
#define SM_OM  13440
#define SM_TOTAL ((13440 + 128 * 27) * 4)   // 67584 B

// quad-packed bf16 hi/lo weights
__device__ uint32_t g_wBp[9 * DM_TAP];
__device__ uint32_t g_wOp[9 * OC_TAP];

// ---------------------------------------------------------------------------
__device__ __forceinline__ uint32_t pack_bf(float ve, float vo) {
    __nv_bfloat162 h2 = __floats2bfloat162_rn(ve, vo);
    return *reinterpret_cast<uint32_t*>(&h2);
}
__device__ __forceinline__ void split_pair(float ve, float vo,
                                           uint32_t& hp, uint32_t& lp) {
    hp = pack_bf(ve, vo);
    const float fe = __uint_as_float(hp << 16);
    const float fo = __uint_as_float(hp & 0xFFFF0000u);
    lp = pack_bf(ve - fe, vo - fo);
}
__device__ __forceinline__ void mmabf(float* d, const uint32_t* a,
                                      uint32_t b0, uint32_t b1) {
    asm volatile(
        "mma.sync.aligned.m16n8k16.row.col.f32.bf16.bf16.f32 "
        "{%0,%1,%2,%3}, {%4,%5,%6,%7}, {%8,%9}, {%0,%1,%2,%3};"
        : "+f"(d[0]), "+f"(d[1]), "+f"(d[2]), "+f"(d[3])
        : "r"(a[0]), "r"(a[1]), "r"(a[2]), "r"(a[3]), "r"(b0), "r"(b1));
}

// ---------------------------------------------------------------------------
// prep: quad-packed bf16 hi/lo weight images (unchanged from round 12).
// ---------------------------------------------------------------------------
__global__ void prep_weights_kernel(const float* __restrict__ w,
                                    const float* __restrict__ w_off)
{
    int i = blockIdx.x * 256 + threadIdx.x;
    if (i < 9 * 64 * 16) {                        // main: (tap, co, kk, t)
        int tap = i / 1024;
        int rem = i - tap * 1024;
        int co  = rem >> 4;
        int kk  = (rem >> 2) & 3;
        int t   = rem & 3;
        int c0  = kk * 16 + 2 * t;
        float v0 = w[(co * 64 + c0)     * 9 + tap];
        float v1 = w[(co * 64 + c0 + 1) * 9 + tap];
        float v8 = w[(co * 64 + c0 + 8) * 9 + tap];
        float v9 = w[(co * 64 + c0 + 9) * 9 + tap];
        uint32_t h0, l0, h8, l8;
        split_pair(v0, v1, h0, l0);
        split_pair(v8, v9, h8, l8);
        uint32_t* q = g_wBp + (size_t)tap * DM_TAP + kk * DM_SK + t * DM_ST + co * 4;
        q[0] = h0; q[1] = h8; q[2] = l0; q[3] = l8;
    } else if (i < 9 * 64 * 16 + 9 * 32 * 16) {   // offset: (tap, oc<32, kk, t)
        int j   = i - 9 * 64 * 16;
        int tap = j / 512;
        int rem = j - tap * 512;
        int oc  = rem >> 4;
        int kk  = (rem >> 2) & 3;
        int t   = rem & 3;
        int c0  = kk * 16 + 2 * t;
        float v0 = (oc < 27) ? w_off[(oc * 64 + c0)     * 9 + tap] : 0.0f;
        float v1 = (oc < 27) ? w_off[(oc * 64 + c0 + 1) * 9 + tap] : 0.0f;
        float v8 = (oc < 27) ? w_off[(oc * 64 + c0 + 8) * 9 + tap] : 0.0f;
        float v9 = (oc < 27) ? w_off[(oc * 64 + c0 + 9) * 9 + tap] : 0.0f;
        uint32_t h0, l0, h8, l8;
        split_pair(v0, v1, h0, l0);
        split_pair(v8, v9, h8, l8);
        uint32_t* q = g_wOp + (size_t)tap * OC_TAP + kk * OC_SK + t * OC_ST + oc * 4;
        q[0] = h0; q[1] = h8; q[2] = l0; q[3] = l8;
    }
}

// ---------------------------------------------------------------------------
// Fused kernel: phase A = offset/mask conv -> om in smem; phase B = dcn GEMM.
// 128 threads = [128 pix (M)] tile; bf16 3-term MMA throughout.
// ---------------------------------------------------------------------------
__global__ __launch_bounds__(128, 3) void fused_dcn_kernel(
    const float* __restrict__ x,
    const float* __restrict__ b_off,
    const float* __restrict__ bias,
    float* __restrict__ out)
{
    extern __shared__ uint32_t smu[];
    uint32_t* Ah  = smu + SM_AH;
    uint32_t* Al  = smu + SM_AL;
    uint32_t* Bp  = smu + SM_BP;
    float*    omf = (float*)(smu + SM_OM);   // [128 pix][27]

    const int tid  = threadIdx.x;
    const int wid  = tid >> 5;
    const int lid  = tid & 31;
    const int g    = lid >> 2;
    const int t    = lid & 3;
    const int hblk = blockIdx.x;
    const int h    = blockIdx.y;
    const int b    = blockIdx.z;
    const int wo   = hblk * 128 + tid;

    const float* xb = x + (size_t)b * CHI * HW;

    // =====================  PHASE A: offset/mask conv  =====================
    {
        float acc[2][4][4];
        #pragma unroll
        for (int m = 0; m < 2; m++)
            #pragma unroll
            for (int n = 0; n < 4; n++)
                #pragma unroll
                for (int e = 0; e < 4; e++) acc[m][n][e] = 0.0f;

        #pragma unroll 1
        for (int tap = 0; tap < 9; tap++) {
            if (tap) __syncthreads();

            // ---- copy packed B (2176 u32 = 544 uint4) ----
            {
                const uint4* bs = (const uint4*)(g_wOp + (size_t)tap * OC_TAP);
                uint4* bd = (uint4*)Bp;
                #pragma unroll
                for (int j = 0; j < 5; j++) {
                    const int lin = tid + j * 128;
                    if (lin < OC_TAP / 4) bd[lin] = bs[lin];
                }
            }

            // ---- A tile: shifted input, bf16 hi/lo split at load ----
            const int y  = h  - 1 + tap / 3;
            const int xv = wo - 1 + tap % 3;
            const bool valid = (y >= 0) && (y < H_) && (xv >= 0) && (xv < W_);
            const float* xp = xb + y * W_ + xv;
            #pragma unroll
            for (int j2 = 0; j2 < 8; j2++) {
                float v[8];
                #pragma unroll
                for (int e = 0; e < 8; e++)
                    v[e] = valid ? __ldg(xp + (j2 * 8 + e) * HW) : 0.0f;
                uint4 hq, lq;
                split_pair(v[0], v[1], hq.x, lq.x);
                split_pair(v[2], v[3], hq.y, lq.y);
                split_pair(v[4], v[5], hq.z, lq.z);
                split_pair(v[6], v[7], hq.w, lq.w);
                *(uint4*)(Ah + tid * AS_U + j2 * 4) = hq;
                *(uint4*)(Al + tid * AS_U + j2 * 4) = lq;
            }

            __syncthreads();

            // ---- MMA: 4 k16-steps x 4 n-frags x (2m x 3 terms) ----
            #pragma unroll
            for (int kk = 0; kk < 4; kk++) {
                uint32_t ah[2][4], al[2][4];
                #pragma unroll
                for (int mi = 0; mi < 2; mi++) {
                    const int base = (wid * 32 + mi * 16 + g) * AS_U + kk * 8 + t;
                    ah[mi][0] = Ah[base];
                    ah[mi][1] = Ah[base + 8 * AS_U];
                    ah[mi][2] = Ah[base + 4];
                    ah[mi][3] = Ah[base + 8 * AS_U + 4];
                    al[mi][0] = Al[base];
                    al[mi][1] = Al[base + 8 * AS_U];
                    al[mi][2] = Al[base + 4];
                    al[mi][3] = Al[base + 8 * AS_U + 4];
                }
                const uint32_t* bq_base = Bp + kk * OC_SK + t * OC_ST;
                #pragma unroll
                for (int n = 0; n < 4; n++) {
                    const uint4 bq = *(const uint4*)(bq_base + (n * 8 + g) * 4);
                    mmabf(acc[0][n], ah[0], bq.x, bq.y);
                    mmabf(acc[1][n], ah[1], bq.x, bq.y);
                    mmabf(acc[0][n], al[0], bq.x, bq.y);
                    mmabf(acc[1][n], al[1], bq.x, bq.y);
                    mmabf(acc[0][n], ah[0], bq.z, bq.w);
                    mmabf(acc[1][n], ah[1], bq.z, bq.w);
                }
            }
        }

        // ---- epilogue A: fragments -> om smem [pixel][27], + b_off ----
        // fragment (mi,n,e) at lane (g,t): pixel = wid*32+mi*16+g (+8 for e>=2),
        //                                  oc    = n*8+2t (+1 for odd e)
        #pragma unroll
        for (int n = 0; n < 4; n++) {
            const int oc = n * 8 + 2 * t;
            const float b0 = (oc     < 27) ? __ldg(b_off + oc)     : 0.0f;
            const float b1 = (oc + 1 < 27) ? __ldg(b_off + oc + 1) : 0.0f;
            #pragma unroll
            for (int mi = 0; mi < 2; mi++) {
                const int p = wid * 32 + mi * 16 + g;
                if (oc < 27) {
                    omf[p * 27 + oc]       = acc[mi][n][0] + b0;
                    omf[(p + 8) * 27 + oc] = acc[mi][n][2] + b0;
                }
                if (oc + 1 < 27) {
                    omf[p * 27 + oc + 1]       = acc[mi][n][1] + b1;
                    omf[(p + 8) * 27 + oc + 1] = acc[mi][n][3] + b1;
                }
            }
        }
    }
    __syncthreads();     // om complete; A/B regions free for phase B

    // =====================  PHASE B: deformable conv  ======================
    float acc[2][8][4];
    #pragma unroll
    for (int m = 0; m < 2; m++)
        #pragma unroll
        for (int n = 0; n < 8; n++)
            #pragma unroll
            for (int e = 0; e < 4; e++) acc[m][n][e] = 0.0f;

    const float* omp = omf + tid * 27;   // this thread's pixel

    #pragma unroll 1
    for (int tap = 0; tap < 9; tap++) {
        if (tap) __syncthreads();

        // ---- copy packed B (4224 u32 = 1056 uint4) ----
        {
            const uint4* bs = (const uint4*)(g_wBp + (size_t)tap * DM_TAP);
            uint4* bd = (uint4*)Bp;
            #pragma unroll
            for (int j = 0; j < 9; j++) {
                const int lin = tid + j * 128;
                if (lin < DM_TAP / 4) bd[lin] = bs[lin];
            }
        }

        // ---- sampling params (om from smem) ----
        const float oy = omp[2 * tap];
        const float ox = omp[2 * tap + 1];
        const float mz = omp[18 + tap];
        const float m  = 1.0f / (1.0f + expf(-mz));

        const float sy = (float)(h  - 1 + tap / 3) + oy;
        const float sx = (float)(wo - 1 + tap % 3) + ox;

        const float y0f = floorf(sy);
        const float x0f = floorf(sx);
        const float dy  = sy - y0f;
        const float dx  = sx - x0f;
        const int y0 = (int)y0f, x0 = (int)x0f;
        const int y1 = y0 + 1,  x1 = x0 + 1;

        const bool vy0 = (y0 >= 0) && (y0 < H_);
        const bool vy1 = (y1 >= 0) && (y1 < H_);
        const bool vx0 = (x0 >= 0) && (x0 < W_);
        const bool vx1 = (x1 >= 0) && (x1 < W_);

        float w00 = (1.0f - dy) * (1.0f - dx) * m;
        float w01 = (1.0f - dy) * dx * m;
        float w10 = dy * (1.0f - dx) * m;
        float w11 = dy * dx * m;
        if (!(vy0 && vx0)) w00 = 0.0f;
        if (!(vy0 && vx1)) w01 = 0.0f;
        if (!(vy1 && vx0)) w10 = 0.0f;
        if (!(vy1 && vx1)) w11 = 0.0f;

        const int cy0 = min(max(y0, 0), H_ - 1);
        const int cy1 = min(max(y1, 0), H_ - 1);
        const int cx0 = min(max(x0, 0), W_ - 1);
        const int cx1 = min(max(x1, 0), W_ - 1);

        const float* p00 = xb + cy0 * W_ + cx0;
        const float* p01 = xb + cy0 * W_ + cx1;
        const float* p10 = xb + cy1 * W_ + cx0;
        const float* p11 = xb + cy1 * W_ + cx1;

        // ---- gather + bilinear + bf16 split: 64 ci -> Ah/Al[tid] ----
        #pragma unroll
        for (int j2 = 0; j2 < 8; j2++) {
            float v[8];
            #pragma unroll
            for (int e = 0; e < 8; e++) {
                const int ci = j2 * 8 + e;
                v[e] = w00 * __ldg(p00 + ci * HW)
                     + w01 * __ldg(p01 + ci * HW)
                     + w10 * __ldg(p10 + ci * HW)
                     + w11 * __ldg(p11 + ci * HW);
            }
            uint4 hq, lq;
            split_pair(v[0], v[1], hq.x, lq.x);
            split_pair(v[2], v[3], hq.y, lq.y);
            split_pair(v[4], v[5], hq.z, lq.z);
            split_pair(v[6], v[7], hq.w, lq.w);
            *(uint4*)(Ah + tid * AS_U + j2 * 4) = hq;
            *(uint4*)(Al + tid * AS_U + j2 * 4) = lq;
        }

        __syncthreads();

        // ---- MMA: 4 k16-steps x 8 n-frags x (2m x 3 terms) ----
        #pragma unroll
        for (int kk = 0; kk < 4; kk++) {
            uint32_t ah[2][4], al[2][4];
            #pragma unroll
            for (int mi = 0; mi < 2; mi++) {
                const int base = (wid * 32 + mi * 16 + g) * AS_U + kk * 8 + t;
                ah[mi][0] = Ah[base];
                ah[mi][1] = Ah[base + 8 * AS_U];
                ah[mi][2] = Ah[base + 4];
                ah[mi][3] = Ah[base + 8 * AS_U + 4];
                al[mi][0] = Al[base];
                al[mi][1] = Al[base + 8 * AS_U];
                al[mi][2] = Al[base + 4];
                al[mi][3] = Al[base + 8 * AS_U + 4];
            }
            const uint32_t* bq_base = Bp + kk * DM_SK + t * DM_ST;
            #pragma unroll
            for (int n = 0; n < 8; n++) {
                const uint4 bq = *(const uint4*)(bq_base + (n * 8 + g) * 4);
                mmabf(acc[0][n], ah[0], bq.x, bq.y);
                mmabf(acc[1][n], ah[1], bq.x, bq.y);
                mmabf(acc[0][n], al[0], bq.x, bq.y);
                mmabf(acc[1][n], al[1], bq.x, bq.y);
                mmabf(acc[0][n], ah[0], bq.z, bq.w);
                mmabf(acc[1][n], ah[1], bq.z, bq.w);
            }
        }
    }

    // ---- epilogue B: stage D via smem (A region), coalesced stores ----
    __syncthreads();
    float* ds = (float*)smu + wid * 2176;      // [64 co][34] per warp
    #pragma unroll
    for (int mi = 0; mi < 2; mi++) {
        #pragma unroll
        for (int n = 0; n < 8; n++) {
            const int co = n * 8 + 2 * t;
            const int p  = mi * 16 + g;
            ds[co * 34 + p]           = acc[mi][n][0];
            ds[(co + 1) * 34 + p]     = acc[mi][n][1];
            ds[co * 34 + p + 8]       = acc[mi][n][2];
            ds[(co + 1) * 34 + p + 8] = acc[mi][n][3];
        }
    }
    __syncwarp();

    const int pixbase = hblk * 128 + wid * 32;
    #pragma unroll 8
    for (int co = 0; co < 64; co++) {
        out[((size_t)(b * CHO + co) * H_ + h) * W_ + pixbase + lid] =
            ds[co * 34 + lid] + __ldg(bias + co);
    }
}

// ---------------------------------------------------------------------------
extern "C" void kernel_launch(void* const* d_in, const int* in_sizes, int n_in,
                              void* d_out, int out_size)
{
    const float* x      = (const float*)d_in[0];
    const float* w_off  = (const float*)d_in[1];
    const float* b_off  = (const float*)d_in[2];
    const float* weight = (const float*)d_in[3];
    const float* bias   = (const float*)d_in[4];
    float* out = (float*)d_out;

    cudaFuncSetAttribute(fused_dcn_kernel,
                         cudaFuncAttributeMaxDynamicSharedMemorySize, SM_TOTAL);

    const int prep_n = 9 * 64 * 16 + 9 * 32 * 16;
    prep_weights_kernel<<<(prep_n + 255) / 256, 256>>>(weight, w_off);
    fused_dcn_kernel<<<dim3(2, H_, B_), 128, SM_TOTAL>>>(x, b_off, bias, out);
}